// round 10
// baseline (speedup 1.0000x reference)
#include <cuda_runtime.h>
#include <math.h>
#include <stdint.h>

#define BATCH 8
#define NPOS  4096
#define CCH   512
#define HEADS 8
#define DHEAD 64
#define KMAXH 128

// -------- scratch (device globals) --------
__device__ float    g_qf[BATCH * NPOS * CCH];   // raw q feature map (for z)
__device__ float    g_qr[BATCH * NPOS * CCH];   // roped q
__device__ float    g_kr[BATCH * NPOS * CCH];   // roped k
__device__ uint32_t g_xb[BATCH * NPOS * CCH / 2]; // X as bf16x2 (32MB)
__device__ uint32_t g_wb[1024 * 512 / 2];         // W as bf16x2 (1MB)
__device__ float    g_cos[NPOS * 256];
__device__ float    g_sin[NPOS * 256];
__device__ float    g_kv[BATCH * HEADS * DHEAD * DHEAD];
__device__ float    g_ksum[BATCH * CCH];

__device__ __forceinline__ uint32_t pack_bf16x2(float lo, float hi) {
    uint32_t r;
    asm("cvt.rn.bf16x2.f32 %0, %1, %2;" : "=r"(r) : "f"(hi), "f"(lo));
    return r;
}

__device__ __forceinline__ void mma_bf16(float* c, const uint32_t* a, const uint32_t* b) {
    asm volatile(
        "mma.sync.aligned.m16n8k16.row.col.f32.bf16.bf16.f32 "
        "{%0,%1,%2,%3}, {%4,%5,%6,%7}, {%8,%9}, {%0,%1,%2,%3};\n"
        : "+f"(c[0]), "+f"(c[1]), "+f"(c[2]), "+f"(c[3])
        : "r"(a[0]), "r"(a[1]), "r"(a[2]), "r"(a[3]),
          "r"(b[0]), "r"(b[1]));
}

// -------- K0: zero accumulators --------
__global__ void zero_kernel() {
    int i = blockIdx.x * blockDim.x + threadIdx.x;
    if (i < BATCH * HEADS * DHEAD * DHEAD) g_kv[i] = 0.0f;
    if (i < BATCH * CCH) g_ksum[i] = 0.0f;
}

// -------- K0b: rope cos/sin table --------
__global__ void rope_table_kernel() {
    int pos = blockIdx.x;
    int j   = threadIdx.x;
    int jm  = (j < KMAXH) ? j : (j - KMAXH);
    float theta = expf(-(float)jm * (9.210340371976184f / 128.0f));
    float coord = (j < KMAXH) ? (float)(pos >> 6) : (float)(pos & 63);
    float s, c;
    sincosf(coord * theta, &s, &c);
    g_cos[pos * 256 + j] = c;
    g_sin[pos * 256 + j] = s;
}

// -------- K0c: preconvert X and W to bf16 --------
__global__ void convert_kernel(const float* __restrict__ X,
                               const float* __restrict__ W) {
    int i = blockIdx.x * blockDim.x + threadIdx.x;
    if (i < 8388608) {
        float2 v = *(const float2*)(X + (size_t)2 * i);
        g_xb[i] = pack_bf16x2(v.x, v.y);
    } else {
        int j = i - 8388608;
        if (j < 262144) {
            float2 v = *(const float2*)(W + (size_t)2 * j);
            g_wb[j] = pack_bf16x2(v.x, v.y);
        }
    }
}

// ---- K1: bf16 mma GEMM + bias + elu+1 + rope + fused ksum ----
// Grid (8,256). bx<4 -> q half (store raw + roped); bx>=4 -> k half (roped + ksum).
__global__ __launch_bounds__(256) void gemm_qk_bf16_kernel(
    const float* __restrict__ bias) {
    // m16n8k16 fragment smem:
    __shared__ uint32_t As[2][8][32][4];
    __shared__ uint32_t Bs[2][16][32][2];
    __shared__ float sks[128];

    const int bx = blockIdx.x;
    const int by = blockIdx.y;
    const int tid = threadIdx.x;
    const int lane = tid & 31;
    const int warp = tid >> 5;
    const int wm = warp >> 2;
    const int wn = warp & 3;

    if (tid < 128) sks[tid] = 0.0f;

    // gmem word loads: row = tid>>2 (0..63 per pass), wc = (tid&3)*4 (word col 0..15)
    const int lrow = tid >> 2;
    const int wc   = (tid & 3) * 4;

    const uint32_t* Aw = g_xb + (size_t)(by * 128) * 256;
    const uint32_t* Bw = g_wb + (size_t)(bx * 128) * 256;

    float acc[4][4][4];
#pragma unroll
    for (int i = 0; i < 4; i++)
#pragma unroll
        for (int j = 0; j < 4; j++)
#pragma unroll
            for (int r = 0; r < 4; r++) acc[i][j][r] = 0.0f;

    // per-word fragment indices: kp = wc + w (0..15)
    int ksw[4], tigw[4], hiw[4];
#pragma unroll
    for (int w = 0; w < 4; w++) {
        int kp = wc + w;
        ksw[w] = kp >> 3;
        tigw[w] = kp & 3;
        hiw[w] = (kp & 7) >> 2;
    }

    uint4 a2[2], b2[2];
#pragma unroll
    for (int p = 0; p < 2; p++) {
        int row = p * 64 + lrow;
        a2[p] = *(const uint4*)(Aw + (size_t)row * 256 + wc);
        b2[p] = *(const uint4*)(Bw + (size_t)row * 256 + wc);
    }

    for (int iter = 0; iter < 16; iter++) {
        __syncthreads();
#pragma unroll
        for (int p = 0; p < 2; p++) {
            int row = p * 64 + lrow;
            int mtile = row >> 4;
            int rA = row & 15;
            int gA = rA & 7;
            int rowhi = rA >> 3;
            int ntile = row >> 3;
            int gB = row & 7;
            uint32_t wa[4] = {a2[p].x, a2[p].y, a2[p].z, a2[p].w};
            uint32_t wb[4] = {b2[p].x, b2[p].y, b2[p].z, b2[p].w};
#pragma unroll
            for (int w = 0; w < 4; w++) {
                As[ksw[w]][mtile][gA * 4 + tigw[w]][hiw[w] * 2 + rowhi] = wa[w];
                Bs[ksw[w]][ntile][gB * 4 + tigw[w]][hiw[w]] = wb[w];
            }
        }
        __syncthreads();

        if (iter + 1 < 16) {
            int kw0 = (iter + 1) * 16;
#pragma unroll
            for (int p = 0; p < 2; p++) {
                int row = p * 64 + lrow;
                a2[p] = *(const uint4*)(Aw + (size_t)row * 256 + kw0 + wc);
                b2[p] = *(const uint4*)(Bw + (size_t)row * 256 + kw0 + wc);
            }
        }

#pragma unroll
        for (int ks = 0; ks < 2; ks++) {
            uint4 af[4];
            uint2 bf[4];
#pragma unroll
            for (int i = 0; i < 4; i++)
                af[i] = *(const uint4*)&As[ks][wm * 4 + i][lane][0];
#pragma unroll
            for (int j = 0; j < 4; j++)
                bf[j] = *(const uint2*)&Bs[ks][wn * 4 + j][lane][0];
#pragma unroll
            for (int i = 0; i < 4; i++)
#pragma unroll
                for (int j = 0; j < 4; j++)
                    mma_bf16(acc[i][j], (const uint32_t*)&af[i], (const uint32_t*)&bf[j]);
        }
    }

    // ---- epilogue: bias + elu+1 + rope + (k) ksum ----
    const int g = lane >> 2;
    const int t4 = lane & 3;
    const bool isQ = (bx < 4);
    float colsum[4], colsumO[4];
#pragma unroll
    for (int j = 0; j < 4; j++) { colsum[j] = 0.0f; colsumO[j] = 0.0f; }

#pragma unroll
    for (int i = 0; i < 4; i++) {
        int r0 = by * 128 + wm * 64 + i * 16 + g;
        int pos0 = r0 & 4095;
        int pos1 = (r0 + 8) & 4095;
#pragma unroll
        for (int j = 0; j < 4; j++) {
            int cg = bx * 128 + wn * 32 + j * 8 + 2 * t4;
            int cb = cg & 511;          // col within 512
            int jg = cb >> 1;           // rope pair index
            float b0 = bias[cg], b1 = bias[cg + 1];
            float v00 = acc[i][j][0] + b0;
            float v01 = acc[i][j][1] + b1;
            float v10 = acc[i][j][2] + b0;
            float v11 = acc[i][j][3] + b1;
            v00 = (v00 > 0.0f) ? (v00 + 1.0f) : expf(v00);
            v01 = (v01 > 0.0f) ? (v01 + 1.0f) : expf(v01);
            v10 = (v10 > 0.0f) ? (v10 + 1.0f) : expf(v10);
            v11 = (v11 > 0.0f) ? (v11 + 1.0f) : expf(v11);

            float c0 = g_cos[pos0 * 256 + jg], s0 = g_sin[pos0 * 256 + jg];
            float c1 = g_cos[pos1 * 256 + jg], s1 = g_sin[pos1 * 256 + jg];
            float2 rp0 = make_float2(c0 * v00 - s0 * v01, c0 * v01 + s0 * v00);
            float2 rp1 = make_float2(c1 * v10 - s1 * v11, c1 * v11 + s1 * v10);

            if (isQ) {
                *(float2*)&g_qf[(size_t)r0 * 512 + cb] = make_float2(v00, v01);
                *(float2*)&g_qf[(size_t)(r0 + 8) * 512 + cb] = make_float2(v10, v11);
                *(float2*)&g_qr[(size_t)r0 * 512 + cb] = rp0;
                *(float2*)&g_qr[(size_t)(r0 + 8) * 512 + cb] = rp1;
            } else {
                *(float2*)&g_kr[(size_t)r0 * 512 + cb] = rp0;
                *(float2*)&g_kr[(size_t)(r0 + 8) * 512 + cb] = rp1;
                colsum[j]  += v00 + v10;
                colsumO[j] += v01 + v11;
            }
        }
    }

    if (!isQ) {
#pragma unroll
        for (int j = 0; j < 4; j++) {
            int lc = wn * 32 + j * 8 + 2 * t4;
            atomicAdd(&sks[lc], colsum[j]);
            atomicAdd(&sks[lc + 1], colsumO[j]);
        }
        __syncthreads();
        if (tid < 128) {
            int b = by >> 5;
            atomicAdd(&g_ksum[b * 512 + (bx & 3) * 128 + tid], sks[tid]);
        }
    }
}

// -------- K3: kv[b,h,d,e] = (1/n) * sum_n kr[n,d] * x[n,e] --------
// grid: B*H*16 (split-K over n, 256 rows each), 256 threads
__global__ __launch_bounds__(256) void kv_kernel(const float* __restrict__ X) {
    __shared__ float ks[16 * 64];
    __shared__ float vs[16 * 64];

    int blk = blockIdx.x;
    int split = blk & 15;
    int head  = (blk >> 4) & 7;
    int b     = blk >> 7;
    int t  = threadIdx.x;
    int tx = t & 15;
    int ty = t >> 4;

    float acc[4][4];
#pragma unroll
    for (int i = 0; i < 4; i++)
#pragma unroll
        for (int j = 0; j < 4; j++) acc[i][j] = 0.0f;

    int n_base = split * 256;
    for (int c0 = 0; c0 < 256; c0 += 16) {
        int n0 = n_base + c0;
        int row = t >> 4;
        int c4 = (t & 15) * 4;
        size_t base = ((size_t)(b * NPOS + n0 + row)) * 512 + head * 64 + c4;
        *(float4*)&ks[row * 64 + c4] = *(const float4*)(g_kr + base);
        *(float4*)&vs[row * 64 + c4] = *(const float4*)(X + base);
        __syncthreads();

#pragma unroll
        for (int kk = 0; kk < 16; kk++) {
            float a[4], bb[4];
            *(float4*)a  = *(const float4*)&ks[kk * 64 + ty * 4];
            *(float4*)bb = *(const float4*)&vs[kk * 64 + tx * 4];
#pragma unroll
            for (int i = 0; i < 4; i++)
#pragma unroll
                for (int j = 0; j < 4; j++)
                    acc[i][j] = fmaf(a[i], bb[j], acc[i][j]);
        }
        __syncthreads();
    }

    float* kvp = g_kv + (b * 8 + head) * 4096;
#pragma unroll
    for (int i = 0; i < 4; i++)
#pragma unroll
        for (int j = 0; j < 4; j++)
            atomicAdd(&kvp[(ty * 4 + i) * 64 + tx * 4 + j],
                      acc[i][j] * (1.0f / 4096.0f));
}

// -------- K4: out = (qr @ kv) * z,  z = 1/(q . kmean + 1e-6) --------
__global__ __launch_bounds__(256) void out_kernel(float* __restrict__ out) {
    __shared__ float kvs[64 * 64];
    __shared__ float qs[64 * 65];
    __shared__ float zarr[64];
    __shared__ float km[64];

    int blk = blockIdx.x;
    int pchunk = blk & 63;
    int head   = (blk >> 6) & 7;
    int b      = blk >> 9;
    int n0 = pchunk * 64;
    int t = threadIdx.x;

    const float* kvp = g_kv + (b * 8 + head) * 4096;
    for (int i = t; i < 4096; i += 256) kvs[i] = kvp[i];
    if (t < 64) km[t] = g_ksum[b * 512 + head * 64 + t] * (1.0f / 4096.0f);

    // raw q tile -> z
    {
        int pos = t >> 2;
        int cb = (t & 3) * 16;
        const float* src = g_qf + ((size_t)(b * NPOS + n0 + pos)) * 512 + head * 64 + cb;
        float* dq = &qs[pos * 65 + cb];
#pragma unroll
        for (int u = 0; u < 16; u += 4) {
            float4 v = *(const float4*)(src + u);
            dq[u] = v.x; dq[u + 1] = v.y; dq[u + 2] = v.z; dq[u + 3] = v.w;
        }
    }
    __syncthreads();

    if (t < 64) {
        float dot = 0.0f;
#pragma unroll
        for (int d2 = 0; d2 < 64; d2++) dot = fmaf(qs[t * 65 + d2], km[d2], dot);
        zarr[t] = 1.0f / (dot + 1e-6f);
    }
    __syncthreads();

    // roped q tile (overwrite qs)
    {
        int pos = t >> 2;
        int cb = (t & 3) * 16;
        const float* src = g_qr + ((size_t)(b * NPOS + n0 + pos)) * 512 + head * 64 + cb;
        float* dq = &qs[pos * 65 + cb];
#pragma unroll
        for (int u = 0; u < 16; u += 4) {
            float4 v = *(const float4*)(src + u);
            dq[u] = v.x; dq[u + 1] = v.y; dq[u + 2] = v.z; dq[u + 3] = v.w;
        }
    }
    __syncthreads();

    int e = t & 63;
    for (int it = 0; it < 16; it++) {
        int pos = it * 4 + (t >> 6);
        float a2 = 0.0f;
#pragma unroll
        for (int d2 = 0; d2 < 64; d2++)
            a2 = fmaf(qs[pos * 65 + d2], kvs[d2 * 64 + e], a2);
        out[((size_t)(b * NPOS + n0 + pos)) * 512 + head * 64 + e] = a2 * zarr[pos];
    }
}

// -------- K5: LePE depthwise 3x3 conv on x, added into out --------
__global__ void lepe_kernel(const float* __restrict__ X,
                            const float* __restrict__ Wc,
                            const float* __restrict__ Bc,
                            float* __restrict__ out) {
    int idx = blockIdx.x * blockDim.x + threadIdx.x;
    int ch  = idx & 511;
    int rest = idx >> 9;
    int pos = rest & 4095;
    int b = rest >> 12;
    int hi = pos >> 6;
    int wi = pos & 63;

    float acc = Bc[ch];
    const float* wp = Wc + ch * 9;
    const float* xb = X + ((size_t)b * NPOS) * 512 + ch;
#pragma unroll
    for (int ky = 0; ky < 3; ky++) {
        int y = hi + ky - 1;
        if ((unsigned)y >= 64u) continue;
#pragma unroll
        for (int kx = 0; kx < 3; kx++) {
            int xw = wi + kx - 1;
            if ((unsigned)xw >= 64u) continue;
            acc = fmaf(xb[((size_t)(y * 64 + xw)) * 512], wp[ky * 3 + kx], acc);
        }
    }
    out[idx] += acc;
}

// -------- launch --------
extern "C" void kernel_launch(void* const* d_in, const int* in_sizes, int n_in,
                              void* d_out, int out_size) {
    const float* x   = nullptr;
    const float* Wqk = nullptr;
    const float* bqk = nullptr;
    const float* lw  = nullptr;
    const float* lb  = nullptr;
    for (int i = 0; i < n_in; i++) {
        switch (in_sizes[i]) {
            case 16777216: x   = (const float*)d_in[i]; break;
            case 524288:   Wqk = (const float*)d_in[i]; break;
            case 1024:     bqk = (const float*)d_in[i]; break;
            case 4608:     lw  = (const float*)d_in[i]; break;
            case 512:      lb  = (const float*)d_in[i]; break;
            default: break;
        }
    }
    float* out = (float*)d_out;

    zero_kernel<<<1024, 256>>>();
    rope_table_kernel<<<NPOS, 256>>>();
    convert_kernel<<<(8388608 + 262144 + 255) / 256, 256>>>(x, Wqk);
    gemm_qk_bf16_kernel<<<dim3(8, 256), 256>>>(bqk);
    kv_kernel<<<BATCH * HEADS * 16, 256>>>(x);
    out_kernel<<<BATCH * HEADS * 64, 256>>>(out);
    lepe_kernel<<<(BATCH * NPOS * CCH) / 256, 256>>>(x, lw, lb, out);
}

// round 12
// speedup vs baseline: 1.1917x; 1.1917x over previous
#include <cuda_runtime.h>
#include <math.h>
#include <stdint.h>

#define BATCH 8
#define NPOS  4096
#define CCH   512
#define HEADS 8
#define DHEAD 64
#define KMAXH 128

// -------- scratch (device globals) --------
__device__ float    g_qf[BATCH * NPOS * CCH];   // raw q feature map (for z)
__device__ float    g_qr[BATCH * NPOS * CCH];   // roped q
__device__ float    g_kr[BATCH * NPOS * CCH];   // roped k
__device__ uint32_t g_xb[BATCH * NPOS * CCH / 2]; // X as bf16x2 (32MB)
__device__ uint32_t g_wb[1024 * 512 / 2];         // W as bf16x2 (1MB)
__device__ float    g_cos[NPOS * 256];
__device__ float    g_sin[NPOS * 256];
__device__ float    g_kv[BATCH * HEADS * DHEAD * DHEAD];
__device__ float    g_ksum[BATCH * CCH];

__device__ __forceinline__ uint32_t pack_bf16x2(float lo, float hi) {
    uint32_t r;
    asm("cvt.rn.bf16x2.f32 %0, %1, %2;" : "=r"(r) : "f"(hi), "f"(lo));
    return r;
}

__device__ __forceinline__ void mma_bf16(float* c, const uint32_t* a, const uint32_t* b) {
    asm volatile(
        "mma.sync.aligned.m16n8k16.row.col.f32.bf16.bf16.f32 "
        "{%0,%1,%2,%3}, {%4,%5,%6,%7}, {%8,%9}, {%0,%1,%2,%3};\n"
        : "+f"(c[0]), "+f"(c[1]), "+f"(c[2]), "+f"(c[3])
        : "r"(a[0]), "r"(a[1]), "r"(a[2]), "r"(a[3]),
          "r"(b[0]), "r"(b[1]));
}

__device__ __forceinline__ uint32_t smem_addr(const void* p) {
    uint32_t a;
    asm("{ .reg .u64 t; cvta.to.shared.u64 t, %1; cvt.u32.u64 %0, t; }"
        : "=r"(a) : "l"(p));
    return a;
}
__device__ __forceinline__ void cp16(uint32_t dst, const void* src) {
    asm volatile("cp.async.cg.shared.global [%0], [%1], 16;\n"
                 :: "r"(dst), "l"(src) : "memory");
}
__device__ __forceinline__ void cp_commit() {
    asm volatile("cp.async.commit_group;\n" ::: "memory");
}
#define LDSM4(r0, r1, r2, r3, addr) \
    asm volatile("ldmatrix.sync.aligned.m8n8.x4.shared.b16 {%0,%1,%2,%3}, [%4];" \
        : "=r"(r0), "=r"(r1), "=r"(r2), "=r"(r3) : "r"(addr))

// -------- K0: zero accumulators --------
__global__ void zero_kernel() {
    int i = blockIdx.x * blockDim.x + threadIdx.x;
    if (i < BATCH * HEADS * DHEAD * DHEAD) g_kv[i] = 0.0f;
    if (i < BATCH * CCH) g_ksum[i] = 0.0f;
}

// -------- K0b: rope cos/sin table --------
__global__ void rope_table_kernel() {
    int pos = blockIdx.x;
    int j   = threadIdx.x;
    int jm  = (j < KMAXH) ? j : (j - KMAXH);
    float theta = expf(-(float)jm * (9.210340371976184f / 128.0f));
    float coord = (j < KMAXH) ? (float)(pos >> 6) : (float)(pos & 63);
    float s, c;
    sincosf(coord * theta, &s, &c);
    g_cos[pos * 256 + j] = c;
    g_sin[pos * 256 + j] = s;
}

// -------- K0c: preconvert X and W to bf16 --------
__global__ void convert_kernel(const float* __restrict__ X,
                               const float* __restrict__ W) {
    int i = blockIdx.x * blockDim.x + threadIdx.x;
    if (i < 8388608) {
        float2 v = *(const float2*)(X + (size_t)2 * i);
        g_xb[i] = pack_bf16x2(v.x, v.y);
    } else {
        int j = i - 8388608;
        if (j < 262144) {
            float2 v = *(const float2*)(W + (size_t)2 * j);
            g_wb[j] = pack_bf16x2(v.x, v.y);
        }
    }
}

// ---- K1: bf16 mma GEMM (cp.async + ldmatrix) + bias + elu+1 + rope + ksum ----
// Grid (8,256). BM=128, BN=128, BK=64, double-buffered. Warp tile 64x32.
// Dynamic smem: A[s] @ s*32768 (16KB), B[s] @ s*32768+16384. 64KB total.
// Swizzle: 128B rows of 8 16B-units; unit' = unit ^ (row & 7).
#define GQK_SMEM 65536

__global__ __launch_bounds__(256) void gemm_qk_bf16_kernel(
    const float* __restrict__ bias) {
    extern __shared__ uint8_t dsm[];
    __shared__ float sks[128];

    const int bx = blockIdx.x;
    const int by = blockIdx.y;
    const int tid = threadIdx.x;
    const int lane = tid & 31;
    const int warp = tid >> 5;
    const int wm = warp >> 2;
    const int wn = warp & 3;

    if (tid < 128) sks[tid] = 0.0f;

    const uint32_t sb = smem_addr(dsm);
    const uint32_t* Aw = g_xb + (size_t)(by * 128) * 256;
    const uint32_t* Bw = g_wb + (size_t)(bx * 128) * 256;

    // copy mapping: lin = p*256+tid -> row = lin>>3, unit c = lin&7
    const int cr = tid >> 3;        // row base (p adds 32)
    const int cc = tid & 7;

    // ldmatrix per-lane constants
    const int x7 = lane & 7;
    const int cselA = lane >> 4;          // unit +0/+1
    const int cselB = (lane >> 3) & 1;
    uint32_t baseA[4];
#pragma unroll
    for (int i = 0; i < 4; i++) {
        int row = wm * 64 + i * 16 + (lane & 7) + ((lane >> 3) & 1) * 8;
        baseA[i] = (uint32_t)row * 128;
    }
    uint32_t baseB[2];
#pragma unroll
    for (int jp = 0; jp < 2; jp++) {
        int row = wn * 32 + jp * 16 + (lane & 7) + (lane >> 4) * 8;
        baseB[jp] = (uint32_t)row * 128;
    }

    float acc[4][4][4];
#pragma unroll
    for (int i = 0; i < 4; i++)
#pragma unroll
        for (int j = 0; j < 4; j++)
#pragma unroll
            for (int r = 0; r < 4; r++) acc[i][j][r] = 0.0f;

    // ---- issue tile 0 ----
#pragma unroll
    for (int p = 0; p < 4; p++) {
        int r = cr + p * 32;
        uint32_t soff = ((uint32_t)(r * 8 + (cc ^ (r & 7)))) * 16;
        cp16(sb + soff, Aw + (size_t)r * 256 + cc * 4);
        cp16(sb + 16384 + soff, Bw + (size_t)r * 256 + cc * 4);
    }
    cp_commit();

    for (int t = 0; t < 8; t++) {
        const int s = t & 1;
        if (t < 7) {
            const int kw = (t + 1) * 32;
            const uint32_t dstb = sb + (s ^ 1) * 32768;
#pragma unroll
            for (int p = 0; p < 4; p++) {
                int r = cr + p * 32;
                uint32_t soff = ((uint32_t)(r * 8 + (cc ^ (r & 7)))) * 16;
                cp16(dstb + soff, Aw + (size_t)r * 256 + kw + cc * 4);
                cp16(dstb + 16384 + soff, Bw + (size_t)r * 256 + kw + cc * 4);
            }
            cp_commit();
            asm volatile("cp.async.wait_group 1;\n" ::: "memory");
        } else {
            asm volatile("cp.async.wait_group 0;\n" ::: "memory");
        }
        __syncthreads();

        const uint32_t Ab = sb + s * 32768;
        const uint32_t Bb = Ab + 16384;
#pragma unroll
        for (int ks = 0; ks < 4; ks++) {
            const uint32_t offA = ((uint32_t)((ks * 2 + cselA) ^ x7)) * 16;
            const uint32_t offB = ((uint32_t)((ks * 2 + cselB) ^ x7)) * 16;
            uint32_t a[4][4];
#pragma unroll
            for (int i = 0; i < 4; i++)
                LDSM4(a[i][0], a[i][1], a[i][2], a[i][3], Ab + baseA[i] + offA);
            uint32_t bfr[2][4];
#pragma unroll
            for (int jp = 0; jp < 2; jp++)
                LDSM4(bfr[jp][0], bfr[jp][1], bfr[jp][2], bfr[jp][3],
                      Bb + baseB[jp] + offB);
#pragma unroll
            for (int i = 0; i < 4; i++)
#pragma unroll
                for (int j = 0; j < 4; j++)
                    mma_bf16(acc[i][j], a[i], &bfr[j >> 1][(j & 1) * 2]);
        }
        __syncthreads();
    }

    // ---- epilogue: bias + elu+1 + rope + (k) ksum ----
    const int g = lane >> 2;
    const int t4 = lane & 3;
    const bool isQ = (bx < 4);
    float colsum[4], colsumO[4];
#pragma unroll
    for (int j = 0; j < 4; j++) { colsum[j] = 0.0f; colsumO[j] = 0.0f; }

#pragma unroll
    for (int i = 0; i < 4; i++) {
        int r0 = by * 128 + wm * 64 + i * 16 + g;
        int pos0 = r0 & 4095;
        int pos1 = (r0 + 8) & 4095;
#pragma unroll
        for (int j = 0; j < 4; j++) {
            int cg = bx * 128 + wn * 32 + j * 8 + 2 * t4;
            int cb = cg & 511;
            int jg = cb >> 1;
            float b0 = bias[cg], b1 = bias[cg + 1];
            float v00 = acc[i][j][0] + b0;
            float v01 = acc[i][j][1] + b1;
            float v10 = acc[i][j][2] + b0;
            float v11 = acc[i][j][3] + b1;
            v00 = (v00 > 0.0f) ? (v00 + 1.0f) : expf(v00);
            v01 = (v01 > 0.0f) ? (v01 + 1.0f) : expf(v01);
            v10 = (v10 > 0.0f) ? (v10 + 1.0f) : expf(v10);
            v11 = (v11 > 0.0f) ? (v11 + 1.0f) : expf(v11);

            float c0 = g_cos[pos0 * 256 + jg], s0 = g_sin[pos0 * 256 + jg];
            float c1 = g_cos[pos1 * 256 + jg], s1 = g_sin[pos1 * 256 + jg];
            float2 rp0 = make_float2(c0 * v00 - s0 * v01, c0 * v01 + s0 * v00);
            float2 rp1 = make_float2(c1 * v10 - s1 * v11, c1 * v11 + s1 * v10);

            if (isQ) {
                *(float2*)&g_qf[(size_t)r0 * 512 + cb] = make_float2(v00, v01);
                *(float2*)&g_qf[(size_t)(r0 + 8) * 512 + cb] = make_float2(v10, v11);
                *(float2*)&g_qr[(size_t)r0 * 512 + cb] = rp0;
                *(float2*)&g_qr[(size_t)(r0 + 8) * 512 + cb] = rp1;
            } else {
                *(float2*)&g_kr[(size_t)r0 * 512 + cb] = rp0;
                *(float2*)&g_kr[(size_t)(r0 + 8) * 512 + cb] = rp1;
                colsum[j]  += v00 + v10;
                colsumO[j] += v01 + v11;
            }
        }
    }

    if (!isQ) {
#pragma unroll
        for (int j = 0; j < 4; j++) {
            int lc = wn * 32 + j * 8 + 2 * t4;
            atomicAdd(&sks[lc], colsum[j]);
            atomicAdd(&sks[lc + 1], colsumO[j]);
        }
        __syncthreads();
        if (tid < 128) {
            int b = by >> 5;
            atomicAdd(&g_ksum[b * 512 + (bx & 3) * 128 + tid], sks[tid]);
        }
    }
}

// -------- K3: kv[b,h,d,e] = (1/n) * sum_n kr[n,d] * x[n,e] --------
__global__ __launch_bounds__(256) void kv_kernel(const float* __restrict__ X) {
    __shared__ float ks[16 * 64];
    __shared__ float vs[16 * 64];

    int blk = blockIdx.x;
    int split = blk & 15;
    int head  = (blk >> 4) & 7;
    int b     = blk >> 7;
    int t  = threadIdx.x;
    int tx = t & 15;
    int ty = t >> 4;

    float acc[4][4];
#pragma unroll
    for (int i = 0; i < 4; i++)
#pragma unroll
        for (int j = 0; j < 4; j++) acc[i][j] = 0.0f;

    int n_base = split * 256;
    for (int c0 = 0; c0 < 256; c0 += 16) {
        int n0 = n_base + c0;
        int row = t >> 4;
        int c4 = (t & 15) * 4;
        size_t base = ((size_t)(b * NPOS + n0 + row)) * 512 + head * 64 + c4;
        *(float4*)&ks[row * 64 + c4] = *(const float4*)(g_kr + base);
        *(float4*)&vs[row * 64 + c4] = *(const float4*)(X + base);
        __syncthreads();

#pragma unroll
        for (int kk = 0; kk < 16; kk++) {
            float a[4], bb[4];
            *(float4*)a  = *(const float4*)&ks[kk * 64 + ty * 4];
            *(float4*)bb = *(const float4*)&vs[kk * 64 + tx * 4];
#pragma unroll
            for (int i = 0; i < 4; i++)
#pragma unroll
                for (int j = 0; j < 4; j++)
                    acc[i][j] = fmaf(a[i], bb[j], acc[i][j]);
        }
        __syncthreads();
    }

    float* kvp = g_kv + (b * 8 + head) * 4096;
#pragma unroll
    for (int i = 0; i < 4; i++)
#pragma unroll
        for (int j = 0; j < 4; j++)
            atomicAdd(&kvp[(ty * 4 + i) * 64 + tx * 4 + j],
                      acc[i][j] * (1.0f / 4096.0f));
}

// -------- K4: out = (qr @ kv) * z,  z = 1/(q . kmean + 1e-6) --------
__global__ __launch_bounds__(256) void out_kernel(float* __restrict__ out) {
    __shared__ float kvs[64 * 64];
    __shared__ float qs[64 * 65];
    __shared__ float zarr[64];
    __shared__ float km[64];

    int blk = blockIdx.x;
    int pchunk = blk & 63;
    int head   = (blk >> 6) & 7;
    int b      = blk >> 9;
    int n0 = pchunk * 64;
    int t = threadIdx.x;

    const float* kvp = g_kv + (b * 8 + head) * 4096;
    for (int i = t; i < 4096; i += 256) kvs[i] = kvp[i];
    if (t < 64) km[t] = g_ksum[b * 512 + head * 64 + t] * (1.0f / 4096.0f);

    {
        int pos = t >> 2;
        int cb = (t & 3) * 16;
        const float* src = g_qf + ((size_t)(b * NPOS + n0 + pos)) * 512 + head * 64 + cb;
        float* dq = &qs[pos * 65 + cb];
#pragma unroll
        for (int u = 0; u < 16; u += 4) {
            float4 v = *(const float4*)(src + u);
            dq[u] = v.x; dq[u + 1] = v.y; dq[u + 2] = v.z; dq[u + 3] = v.w;
        }
    }
    __syncthreads();

    if (t < 64) {
        float dot = 0.0f;
#pragma unroll
        for (int d2 = 0; d2 < 64; d2++) dot = fmaf(qs[t * 65 + d2], km[d2], dot);
        zarr[t] = 1.0f / (dot + 1e-6f);
    }
    __syncthreads();

    {
        int pos = t >> 2;
        int cb = (t & 3) * 16;
        const float* src = g_qr + ((size_t)(b * NPOS + n0 + pos)) * 512 + head * 64 + cb;
        float* dq = &qs[pos * 65 + cb];
#pragma unroll
        for (int u = 0; u < 16; u += 4) {
            float4 v = *(const float4*)(src + u);
            dq[u] = v.x; dq[u + 1] = v.y; dq[u + 2] = v.z; dq[u + 3] = v.w;
        }
    }
    __syncthreads();

    int e = t & 63;
    for (int it = 0; it < 16; it++) {
        int pos = it * 4 + (t >> 6);
        float a2 = 0.0f;
#pragma unroll
        for (int d2 = 0; d2 < 64; d2++)
            a2 = fmaf(qs[pos * 65 + d2], kvs[d2 * 64 + e], a2);
        out[((size_t)(b * NPOS + n0 + pos)) * 512 + head * 64 + e] = a2 * zarr[pos];
    }
}

// -------- K5: LePE depthwise 3x3 conv on x, added into out --------
__global__ void lepe_kernel(const float* __restrict__ X,
                            const float* __restrict__ Wc,
                            const float* __restrict__ Bc,
                            float* __restrict__ out) {
    int idx = blockIdx.x * blockDim.x + threadIdx.x;
    int ch  = idx & 511;
    int rest = idx >> 9;
    int pos = rest & 4095;
    int b = rest >> 12;
    int hi = pos >> 6;
    int wi = pos & 63;

    float acc = Bc[ch];
    const float* wp = Wc + ch * 9;
    const float* xb = X + ((size_t)b * NPOS) * 512 + ch;
#pragma unroll
    for (int ky = 0; ky < 3; ky++) {
        int y = hi + ky - 1;
        if ((unsigned)y >= 64u) continue;
#pragma unroll
        for (int kx = 0; kx < 3; kx++) {
            int xw = wi + kx - 1;
            if ((unsigned)xw >= 64u) continue;
            acc = fmaf(xb[((size_t)(y * 64 + xw)) * 512], wp[ky * 3 + kx], acc);
        }
    }
    out[idx] += acc;
}

// -------- launch --------
extern "C" void kernel_launch(void* const* d_in, const int* in_sizes, int n_in,
                              void* d_out, int out_size) {
    const float* x   = nullptr;
    const float* Wqk = nullptr;
    const float* bqk = nullptr;
    const float* lw  = nullptr;
    const float* lb  = nullptr;
    for (int i = 0; i < n_in; i++) {
        switch (in_sizes[i]) {
            case 16777216: x   = (const float*)d_in[i]; break;
            case 524288:   Wqk = (const float*)d_in[i]; break;
            case 1024:     bqk = (const float*)d_in[i]; break;
            case 4608:     lw  = (const float*)d_in[i]; break;
            case 512:      lb  = (const float*)d_in[i]; break;
            default: break;
        }
    }
    float* out = (float*)d_out;

    cudaFuncSetAttribute(gemm_qk_bf16_kernel,
                         cudaFuncAttributeMaxDynamicSharedMemorySize, GQK_SMEM);

    zero_kernel<<<1024, 256>>>();
    rope_table_kernel<<<NPOS, 256>>>();
    convert_kernel<<<(8388608 + 262144 + 255) / 256, 256>>>(x, Wqk);
    gemm_qk_bf16_kernel<<<dim3(8, 256), 256, GQK_SMEM>>>(bqk);
    kv_kernel<<<BATCH * HEADS * 16, 256>>>(x);
    out_kernel<<<BATCH * HEADS * 64, 256>>>(out);
    lepe_kernel<<<(BATCH * NPOS * CCH) / 256, 256>>>(x, lw, lb, out);
}

// round 13
// speedup vs baseline: 1.4812x; 1.2429x over previous
#include <cuda_runtime.h>
#include <math.h>
#include <stdint.h>

#define BATCH 8
#define NPOS  4096
#define CCH   512
#define HEADS 8
#define DHEAD 64
#define KMAXH 128

// -------- scratch (device globals) --------
__device__ float    g_qf[BATCH * NPOS * CCH];   // raw q feature map (for z)
__device__ float    g_qr[BATCH * NPOS * CCH];   // roped q
__device__ float    g_kr[BATCH * NPOS * CCH];   // roped k
__device__ uint32_t g_xb[BATCH * NPOS * CCH / 2]; // X as bf16x2 (32MB)
__device__ uint32_t g_wb[1024 * 512 / 2];         // W as bf16x2 (1MB)
__device__ float    g_cos[NPOS * 256];
__device__ float    g_sin[NPOS * 256];
__device__ float    g_kv[BATCH * HEADS * DHEAD * DHEAD];
__device__ float    g_ksum[BATCH * CCH];

__device__ __forceinline__ uint32_t pack_bf16x2(float lo, float hi) {
    uint32_t r;
    asm("cvt.rn.bf16x2.f32 %0, %1, %2;" : "=r"(r) : "f"(hi), "f"(lo));
    return r;
}

__device__ __forceinline__ void mma_bf16(float* c, const uint32_t* a, const uint32_t* b) {
    asm volatile(
        "mma.sync.aligned.m16n8k16.row.col.f32.bf16.bf16.f32 "
        "{%0,%1,%2,%3}, {%4,%5,%6,%7}, {%8,%9}, {%0,%1,%2,%3};\n"
        : "+f"(c[0]), "+f"(c[1]), "+f"(c[2]), "+f"(c[3])
        : "r"(a[0]), "r"(a[1]), "r"(a[2]), "r"(a[3]),
          "r"(b[0]), "r"(b[1]));
}

__device__ __forceinline__ uint32_t smem_addr(const void* p) {
    uint32_t a;
    asm("{ .reg .u64 t; cvta.to.shared.u64 t, %1; cvt.u32.u64 %0, t; }"
        : "=r"(a) : "l"(p));
    return a;
}
__device__ __forceinline__ void cp16(uint32_t dst, const void* src) {
    asm volatile("cp.async.cg.shared.global [%0], [%1], 16;\n"
                 :: "r"(dst), "l"(src) : "memory");
}
__device__ __forceinline__ void cp_commit() {
    asm volatile("cp.async.commit_group;\n" ::: "memory");
}
#define LDSM4(r0, r1, r2, r3, addr) \
    asm volatile("ldmatrix.sync.aligned.m8n8.x4.shared.b16 {%0,%1,%2,%3}, [%4];" \
        : "=r"(r0), "=r"(r1), "=r"(r2), "=r"(r3) : "r"(addr))

// -------- K0: zero accumulators --------
__global__ void zero_kernel() {
    int i = blockIdx.x * blockDim.x + threadIdx.x;
    if (i < BATCH * HEADS * DHEAD * DHEAD) g_kv[i] = 0.0f;
    if (i < BATCH * CCH) g_ksum[i] = 0.0f;
}

// -------- K0b: rope cos/sin table --------
__global__ void rope_table_kernel() {
    int pos = blockIdx.x;
    int j   = threadIdx.x;
    int jm  = (j < KMAXH) ? j : (j - KMAXH);
    float theta = expf(-(float)jm * (9.210340371976184f / 128.0f));
    float coord = (j < KMAXH) ? (float)(pos >> 6) : (float)(pos & 63);
    float s, c;
    sincosf(coord * theta, &s, &c);
    g_cos[pos * 256 + j] = c;
    g_sin[pos * 256 + j] = s;
}

// -------- K0c: preconvert X and W to bf16 --------
__global__ void convert_kernel(const float* __restrict__ X,
                               const float* __restrict__ W) {
    int i = blockIdx.x * blockDim.x + threadIdx.x;
    if (i < 8388608) {
        float2 v = *(const float2*)(X + (size_t)2 * i);
        g_xb[i] = pack_bf16x2(v.x, v.y);
    } else {
        int j = i - 8388608;
        if (j < 262144) {
            float2 v = *(const float2*)(W + (size_t)2 * j);
            g_wb[j] = pack_bf16x2(v.x, v.y);
        }
    }
}

// ---- K1: bf16 mma GEMM (cp.async + ldmatrix) + bias + elu+1 + rope + ksum ----
#define GQK_SMEM 65536

__global__ __launch_bounds__(256) void gemm_qk_bf16_kernel(
    const float* __restrict__ bias) {
    extern __shared__ uint8_t dsm[];
    __shared__ float sks[128];

    const int bx = blockIdx.x;
    const int by = blockIdx.y;
    const int tid = threadIdx.x;
    const int lane = tid & 31;
    const int warp = tid >> 5;
    const int wm = warp >> 2;
    const int wn = warp & 3;

    if (tid < 128) sks[tid] = 0.0f;

    const uint32_t sb = smem_addr(dsm);
    const uint32_t* Aw = g_xb + (size_t)(by * 128) * 256;
    const uint32_t* Bw = g_wb + (size_t)(bx * 128) * 256;

    const int cr = tid >> 3;
    const int cc = tid & 7;

    const int x7 = lane & 7;
    const int cselA = lane >> 4;
    const int cselB = (lane >> 3) & 1;
    uint32_t baseA[4];
#pragma unroll
    for (int i = 0; i < 4; i++) {
        int row = wm * 64 + i * 16 + (lane & 7) + ((lane >> 3) & 1) * 8;
        baseA[i] = (uint32_t)row * 128;
    }
    uint32_t baseB[2];
#pragma unroll
    for (int jp = 0; jp < 2; jp++) {
        int row = wn * 32 + jp * 16 + (lane & 7) + (lane >> 4) * 8;
        baseB[jp] = (uint32_t)row * 128;
    }

    float acc[4][4][4];
#pragma unroll
    for (int i = 0; i < 4; i++)
#pragma unroll
        for (int j = 0; j < 4; j++)
#pragma unroll
            for (int r = 0; r < 4; r++) acc[i][j][r] = 0.0f;

#pragma unroll
    for (int p = 0; p < 4; p++) {
        int r = cr + p * 32;
        uint32_t soff = ((uint32_t)(r * 8 + (cc ^ (r & 7)))) * 16;
        cp16(sb + soff, Aw + (size_t)r * 256 + cc * 4);
        cp16(sb + 16384 + soff, Bw + (size_t)r * 256 + cc * 4);
    }
    cp_commit();

    for (int t = 0; t < 8; t++) {
        const int s = t & 1;
        if (t < 7) {
            const int kw = (t + 1) * 32;
            const uint32_t dstb = sb + (s ^ 1) * 32768;
#pragma unroll
            for (int p = 0; p < 4; p++) {
                int r = cr + p * 32;
                uint32_t soff = ((uint32_t)(r * 8 + (cc ^ (r & 7)))) * 16;
                cp16(dstb + soff, Aw + (size_t)r * 256 + kw + cc * 4);
                cp16(dstb + 16384 + soff, Bw + (size_t)r * 256 + kw + cc * 4);
            }
            cp_commit();
            asm volatile("cp.async.wait_group 1;\n" ::: "memory");
        } else {
            asm volatile("cp.async.wait_group 0;\n" ::: "memory");
        }
        __syncthreads();

        const uint32_t Ab = sb + s * 32768;
        const uint32_t Bb = Ab + 16384;
#pragma unroll
        for (int ks = 0; ks < 4; ks++) {
            const uint32_t offA = ((uint32_t)((ks * 2 + cselA) ^ x7)) * 16;
            const uint32_t offB = ((uint32_t)((ks * 2 + cselB) ^ x7)) * 16;
            uint32_t a[4][4];
#pragma unroll
            for (int i = 0; i < 4; i++)
                LDSM4(a[i][0], a[i][1], a[i][2], a[i][3], Ab + baseA[i] + offA);
            uint32_t bfr[2][4];
#pragma unroll
            for (int jp = 0; jp < 2; jp++)
                LDSM4(bfr[jp][0], bfr[jp][1], bfr[jp][2], bfr[jp][3],
                      Bb + baseB[jp] + offB);
#pragma unroll
            for (int i = 0; i < 4; i++)
#pragma unroll
                for (int j = 0; j < 4; j++)
                    mma_bf16(acc[i][j], a[i], &bfr[j >> 1][(j & 1) * 2]);
        }
        __syncthreads();
    }

    // ---- epilogue: bias + elu+1 + rope + (k) ksum ----
    const int g = lane >> 2;
    const int t4 = lane & 3;
    const bool isQ = (bx < 4);
    float colsum[4], colsumO[4];
#pragma unroll
    for (int j = 0; j < 4; j++) { colsum[j] = 0.0f; colsumO[j] = 0.0f; }

#pragma unroll
    for (int i = 0; i < 4; i++) {
        int r0 = by * 128 + wm * 64 + i * 16 + g;
        int pos0 = r0 & 4095;
        int pos1 = (r0 + 8) & 4095;
#pragma unroll
        for (int j = 0; j < 4; j++) {
            int cg = bx * 128 + wn * 32 + j * 8 + 2 * t4;
            int cb = cg & 511;
            int jg = cb >> 1;
            float b0 = bias[cg], b1 = bias[cg + 1];
            float v00 = acc[i][j][0] + b0;
            float v01 = acc[i][j][1] + b1;
            float v10 = acc[i][j][2] + b0;
            float v11 = acc[i][j][3] + b1;
            v00 = (v00 > 0.0f) ? (v00 + 1.0f) : expf(v00);
            v01 = (v01 > 0.0f) ? (v01 + 1.0f) : expf(v01);
            v10 = (v10 > 0.0f) ? (v10 + 1.0f) : expf(v10);
            v11 = (v11 > 0.0f) ? (v11 + 1.0f) : expf(v11);

            float c0 = g_cos[pos0 * 256 + jg], s0 = g_sin[pos0 * 256 + jg];
            float c1 = g_cos[pos1 * 256 + jg], s1 = g_sin[pos1 * 256 + jg];
            float2 rp0 = make_float2(c0 * v00 - s0 * v01, c0 * v01 + s0 * v00);
            float2 rp1 = make_float2(c1 * v10 - s1 * v11, c1 * v11 + s1 * v10);

            if (isQ) {
                *(float2*)&g_qf[(size_t)r0 * 512 + cb] = make_float2(v00, v01);
                *(float2*)&g_qf[(size_t)(r0 + 8) * 512 + cb] = make_float2(v10, v11);
                *(float2*)&g_qr[(size_t)r0 * 512 + cb] = rp0;
                *(float2*)&g_qr[(size_t)(r0 + 8) * 512 + cb] = rp1;
            } else {
                *(float2*)&g_kr[(size_t)r0 * 512 + cb] = rp0;
                *(float2*)&g_kr[(size_t)(r0 + 8) * 512 + cb] = rp1;
                colsum[j]  += v00 + v10;
                colsumO[j] += v01 + v11;
            }
        }
    }

    if (!isQ) {
#pragma unroll
        for (int j = 0; j < 4; j++) {
            int lc = wn * 32 + j * 8 + 2 * t4;
            atomicAdd(&sks[lc], colsum[j]);
            atomicAdd(&sks[lc + 1], colsumO[j]);
        }
        __syncthreads();
        if (tid < 128) {
            int b = by >> 5;
            atomicAdd(&g_ksum[b * 512 + (bx & 3) * 128 + tid], sks[tid]);
        }
    }
}

// -------- K3: kv[b,h,d,e] = (1/n) * sum_n kr[n,d] * x[n,e] --------
__global__ __launch_bounds__(256) void kv_kernel(const float* __restrict__ X) {
    __shared__ float ks[16 * 64];
    __shared__ float vs[16 * 64];

    int blk = blockIdx.x;
    int split = blk & 15;
    int head  = (blk >> 4) & 7;
    int b     = blk >> 7;
    int t  = threadIdx.x;
    int tx = t & 15;
    int ty = t >> 4;

    float acc[4][4];
#pragma unroll
    for (int i = 0; i < 4; i++)
#pragma unroll
        for (int j = 0; j < 4; j++) acc[i][j] = 0.0f;

    int n_base = split * 256;
    for (int c0 = 0; c0 < 256; c0 += 16) {
        int n0 = n_base + c0;
        int row = t >> 4;
        int c4 = (t & 15) * 4;
        size_t base = ((size_t)(b * NPOS + n0 + row)) * 512 + head * 64 + c4;
        *(float4*)&ks[row * 64 + c4] = *(const float4*)(g_kr + base);
        *(float4*)&vs[row * 64 + c4] = *(const float4*)(X + base);
        __syncthreads();

#pragma unroll
        for (int kk = 0; kk < 16; kk++) {
            float a[4], bb[4];
            *(float4*)a  = *(const float4*)&ks[kk * 64 + ty * 4];
            *(float4*)bb = *(const float4*)&vs[kk * 64 + tx * 4];
#pragma unroll
            for (int i = 0; i < 4; i++)
#pragma unroll
                for (int j = 0; j < 4; j++)
                    acc[i][j] = fmaf(a[i], bb[j], acc[i][j]);
        }
        __syncthreads();
    }

    float* kvp = g_kv + (b * 8 + head) * 4096;
#pragma unroll
    for (int i = 0; i < 4; i++)
#pragma unroll
        for (int j = 0; j < 4; j++)
            atomicAdd(&kvp[(ty * 4 + i) * 64 + tx * 4 + j],
                      acc[i][j] * (1.0f / 4096.0f));
}

// -------- K4: out = (qr @ kv) * z,  z = 1/(q . kmean + 1e-6) --------
// 256 thr: thread owns 4 pos x 4 e; per d2: 1 LDS.128 (kv row) + 4 bcast + 16 FMA
__global__ __launch_bounds__(256) void out_kernel(float* __restrict__ out) {
    __shared__ float kvs[64 * 64];
    __shared__ float qs[64 * 65];
    __shared__ float zarr[64];
    __shared__ float km[64];

    int blk = blockIdx.x;
    int pchunk = blk & 63;
    int head   = (blk >> 6) & 7;
    int b      = blk >> 9;
    int n0 = pchunk * 64;
    int t = threadIdx.x;

    const float* kvp = g_kv + (b * 8 + head) * 4096;
    for (int i = t; i < 4096; i += 256) kvs[i] = kvp[i];
    if (t < 64) km[t] = g_ksum[b * 512 + head * 64 + t] * (1.0f / 4096.0f);

    // raw q tile -> z
    {
        int pos = t >> 2;
        int cb = (t & 3) * 16;
        const float* src = g_qf + ((size_t)(b * NPOS + n0 + pos)) * 512 + head * 64 + cb;
        float* dq = &qs[pos * 65 + cb];
#pragma unroll
        for (int u = 0; u < 16; u += 4) {
            float4 v = *(const float4*)(src + u);
            dq[u] = v.x; dq[u + 1] = v.y; dq[u + 2] = v.z; dq[u + 3] = v.w;
        }
    }
    __syncthreads();

    if (t < 64) {
        float dot = 0.0f;
#pragma unroll
        for (int d2 = 0; d2 < 64; d2++) dot = fmaf(qs[t * 65 + d2], km[d2], dot);
        zarr[t] = 1.0f / (dot + 1e-6f);
    }
    __syncthreads();

    // roped q tile (overwrite qs)
    {
        int pos = t >> 2;
        int cb = (t & 3) * 16;
        const float* src = g_qr + ((size_t)(b * NPOS + n0 + pos)) * 512 + head * 64 + cb;
        float* dq = &qs[pos * 65 + cb];
#pragma unroll
        for (int u = 0; u < 16; u += 4) {
            float4 v = *(const float4*)(src + u);
            dq[u] = v.x; dq[u + 1] = v.y; dq[u + 2] = v.z; dq[u + 3] = v.w;
        }
    }
    __syncthreads();

    // matvec: thread = (p0..p0+3) x (e4..e4+3)
    const int e4 = (t & 15) * 4;
    const int p0 = (t >> 4) * 4;
    float a0[4], a1[4], a2[4], a3[4];
#pragma unroll
    for (int j = 0; j < 4; j++) { a0[j] = 0.0f; a1[j] = 0.0f; a2[j] = 0.0f; a3[j] = 0.0f; }

#pragma unroll 8
    for (int d2 = 0; d2 < 64; d2++) {
        float4 kvrow = *(const float4*)&kvs[d2 * 64 + e4];
        float q0 = qs[(p0 + 0) * 65 + d2];
        float q1 = qs[(p0 + 1) * 65 + d2];
        float q2 = qs[(p0 + 2) * 65 + d2];
        float q3 = qs[(p0 + 3) * 65 + d2];
        a0[0] = fmaf(q0, kvrow.x, a0[0]); a0[1] = fmaf(q0, kvrow.y, a0[1]);
        a0[2] = fmaf(q0, kvrow.z, a0[2]); a0[3] = fmaf(q0, kvrow.w, a0[3]);
        a1[0] = fmaf(q1, kvrow.x, a1[0]); a1[1] = fmaf(q1, kvrow.y, a1[1]);
        a1[2] = fmaf(q1, kvrow.z, a1[2]); a1[3] = fmaf(q1, kvrow.w, a1[3]);
        a2[0] = fmaf(q2, kvrow.x, a2[0]); a2[1] = fmaf(q2, kvrow.y, a2[1]);
        a2[2] = fmaf(q2, kvrow.z, a2[2]); a2[3] = fmaf(q2, kvrow.w, a2[3]);
        a3[0] = fmaf(q3, kvrow.x, a3[0]); a3[1] = fmaf(q3, kvrow.y, a3[1]);
        a3[2] = fmaf(q3, kvrow.z, a3[2]); a3[3] = fmaf(q3, kvrow.w, a3[3]);
    }

    float* arr[4] = {a0, a1, a2, a3};
#pragma unroll
    for (int p = 0; p < 4; p++) {
        float zz = zarr[p0 + p];
        float4 res = make_float4(arr[p][0] * zz, arr[p][1] * zz,
                                 arr[p][2] * zz, arr[p][3] * zz);
        *(float4*)&out[((size_t)(b * NPOS + n0 + p0 + p)) * 512 + head * 64 + e4] = res;
    }
}

// -------- K5: LePE depthwise 3x3 conv on x, added into out --------
__global__ void lepe_kernel(const float* __restrict__ X,
                            const float* __restrict__ Wc,
                            const float* __restrict__ Bc,
                            float* __restrict__ out) {
    int idx = blockIdx.x * blockDim.x + threadIdx.x;
    int ch  = idx & 511;
    int rest = idx >> 9;
    int pos = rest & 4095;
    int b = rest >> 12;
    int hi = pos >> 6;
    int wi = pos & 63;

    float acc = Bc[ch];
    const float* wp = Wc + ch * 9;
    const float* xb = X + ((size_t)b * NPOS) * 512 + ch;
#pragma unroll
    for (int ky = 0; ky < 3; ky++) {
        int y = hi + ky - 1;
        if ((unsigned)y >= 64u) continue;
#pragma unroll
        for (int kx = 0; kx < 3; kx++) {
            int xw = wi + kx - 1;
            if ((unsigned)xw >= 64u) continue;
            acc = fmaf(xb[((size_t)(y * 64 + xw)) * 512], wp[ky * 3 + kx], acc);
        }
    }
    out[idx] += acc;
}

// -------- launch --------
extern "C" void kernel_launch(void* const* d_in, const int* in_sizes, int n_in,
                              void* d_out, int out_size) {
    const float* x   = nullptr;
    const float* Wqk = nullptr;
    const float* bqk = nullptr;
    const float* lw  = nullptr;
    const float* lb  = nullptr;
    for (int i = 0; i < n_in; i++) {
        switch (in_sizes[i]) {
            case 16777216: x   = (const float*)d_in[i]; break;
            case 524288:   Wqk = (const float*)d_in[i]; break;
            case 1024:     bqk = (const float*)d_in[i]; break;
            case 4608:     lw  = (const float*)d_in[i]; break;
            case 512:      lb  = (const float*)d_in[i]; break;
            default: break;
        }
    }
    float* out = (float*)d_out;

    cudaFuncSetAttribute(gemm_qk_bf16_kernel,
                         cudaFuncAttributeMaxDynamicSharedMemorySize, GQK_SMEM);

    zero_kernel<<<1024, 256>>>();
    rope_table_kernel<<<NPOS, 256>>>();
    convert_kernel<<<(8388608 + 262144 + 255) / 256, 256>>>(x, Wqk);
    gemm_qk_bf16_kernel<<<dim3(8, 256), 256, GQK_SMEM>>>(bqk);
    kv_kernel<<<BATCH * HEADS * 16, 256>>>(x);
    out_kernel<<<BATCH * HEADS * 64, 256>>>(out);
    lepe_kernel<<<(BATCH * NPOS * CCH) / 256, 256>>>(x, lw, lb, out);
}